// round 11
// baseline (speedup 1.0000x reference)
#include <cuda_runtime.h>
#include <cstdint>

#define Tv 1000
#define Dv 1024
#define NCHUNK 125   // 125 chunks x 8 rows = 1000

// Scratch (__device__ globals per allocation rules)
__device__ float g_part[NCHUNK * 8 * 1024];  // per-chunk partial t-sums
__device__ float g_vsump[16 * 8 * 64];       // 16 j-slice partials of vsum
__device__ float g_row[8 * 1024];            // per-batch output row

// Streaming (evict-first) 128-bit store: keep `out` from polluting L2.
static __device__ __forceinline__ void stcs128(float4* p, float4 v) {
    asm volatile("st.global.cs.v4.f32 [%0], {%1, %2, %3, %4};"
                 :: "l"(p), "f"(v.x), "f"(v.y), "f"(v.z), "f"(v.w) : "memory");
}

// Evict-last (L2-persisting) 128-bit load: keep x resident across replays.
static __device__ __forceinline__ float4 ldpl128(const float4* p, uint64_t pol) {
    float4 v;
    asm volatile("ld.global.L2::cache_hint.v4.f32 {%0, %1, %2, %3}, [%4], %5;"
                 : "=f"(v.x), "=f"(v.y), "=f"(v.z), "=f"(v.w)
                 : "l"(p), "l"(pol));
    return v;
}

// ---------------------------------------------------------------------------
// 1) Partial sums over t: grid (125, 8), 256 threads, 8 batched LDG.128 with
//    L2 evict_last policy on x.
// ---------------------------------------------------------------------------
__global__ void __launch_bounds__(256)
xsum_part_kernel(const float* __restrict__ x)
{
    const int chunk = blockIdx.x;
    const int b     = blockIdx.y;
    const int j4    = threadIdx.x << 2;

    uint64_t pol;
    asm("createpolicy.fractional.L2::evict_last.b64 %0, 1.0;" : "=l"(pol));

    const float4* xp = (const float4*)(x + ((size_t)b * Tv + chunk * 8) * Dv + j4);
    float4 v0 = ldpl128(xp + 0 * 256, pol), v1 = ldpl128(xp + 1 * 256, pol);
    float4 v2 = ldpl128(xp + 2 * 256, pol), v3 = ldpl128(xp + 3 * 256, pol);
    float4 v4 = ldpl128(xp + 4 * 256, pol), v5 = ldpl128(xp + 5 * 256, pol);
    float4 v6 = ldpl128(xp + 6 * 256, pol), v7 = ldpl128(xp + 7 * 256, pol);

    float4 acc;
    acc.x = ((v0.x + v1.x) + (v2.x + v3.x)) + ((v4.x + v5.x) + (v6.x + v7.x));
    acc.y = ((v0.y + v1.y) + (v2.y + v3.y)) + ((v4.y + v5.y) + (v6.y + v7.y));
    acc.z = ((v0.z + v1.z) + (v2.z + v3.z)) + ((v4.z + v5.z) + (v6.z + v7.z));
    acc.w = ((v0.w + v1.w) + (v2.w + v3.w)) + ((v4.w + v5.w) + (v6.w + v7.w));

    *(float4*)(g_part + ((size_t)(chunk * 8 + b)) * Dv + j4) = acc;
}

// ---------------------------------------------------------------------------
// 2) vsum partials: grid (8 b, 16 jb). Each block owns a 64-wide j slice.
// ---------------------------------------------------------------------------
__global__ void __launch_bounds__(256)
vsum_part_kernel(const float* __restrict__ Wv)
{
    __shared__ float xr[4][64];
    __shared__ float xs[64];
    __shared__ float p[4][64];
    const int b   = blockIdx.x;
    const int jb  = blockIdx.y;
    const int tid = threadIdx.x;
    const int j   = tid & 63;
    const int seg = tid >> 6;
    const int jg  = jb * 64;

    {
        const int c0 = seg * 31;
        const int cn = (seg == 3) ? 32 : 31;
        float s = 0.f;
        #pragma unroll 31
        for (int c = 0; c < cn; c++)
            s += g_part[((size_t)((c0 + c) * 8 + b)) * Dv + jg + j];
        xr[seg][j] = s;
    }
    __syncthreads();
    if (seg == 0)
        xs[j] = xr[0][j] + xr[1][j] + xr[2][j] + xr[3][j];
    __syncthreads();

    {
        float acc = 0.f;
        #pragma unroll
        for (int jj = 0; jj < 16; jj++) {
            int jl = seg * 16 + jj;
            acc += xs[jl] * Wv[(size_t)(jg + jl) * 64 + j];
        }
        p[seg][j] = acc;
    }
    __syncthreads();
    if (seg == 0)
        g_vsump[(jb * 8 + b) * 64 + j] = p[0][j] + p[1][j] + p[2][j] + p[3][j];
}

// ---------------------------------------------------------------------------
// 3) row[b,n] = bo[n] + sum_m vs[b, m&63] * Wo[m,n]. grid 32, 256 threads.
// ---------------------------------------------------------------------------
__global__ void __launch_bounds__(256)
row_kernel(const float* __restrict__ Wo, const float* __restrict__ bv,
           const float* __restrict__ bo)
{
    __shared__ float vs[8 * 64];
    __shared__ float part[8][8][32];

    const int n0   = blockIdx.x * 32;
    const int tid  = threadIdx.x;
    const int lane = tid & 31;
    const int wid  = tid >> 5;
    const int n    = n0 + lane;

    #pragma unroll
    for (int i = tid; i < 512; i += 256) {
        int d = i & 63;
        float s = (float)Tv * bv[d];
        #pragma unroll
        for (int jb = 0; jb < 16; jb++)
            s += g_vsump[jb * 512 + i];
        vs[i] = s;
    }
    __syncthreads();

    float acc[8] = {};
    const int mbase = wid * 128;
    #pragma unroll 8
    for (int mm = 0; mm < 64; mm++) {
        float w1 = Wo[(size_t)(mbase + mm) * Dv + n];
        float w2 = Wo[(size_t)(mbase + mm + 64) * Dv + n];
        float w  = w1 + w2;
        #pragma unroll
        for (int b = 0; b < 8; b++)
            acc[b] = fmaf(vs[b * 64 + mm], w, acc[b]);
    }
    #pragma unroll
    for (int b = 0; b < 8; b++)
        part[wid][b][lane] = acc[b];
    __syncthreads();

    {
        int b = wid;
        float s = bo[n];
        #pragma unroll
        for (int w = 0; w < 8; w++)
            s += part[w][b][lane];
        g_row[b * Dv + n] = s;
    }
}

// ---------------------------------------------------------------------------
// 4) Broadcast: grid (125, 8), 256 threads. One float4/thread from g_row,
//    8 streaming STG.128.CS rows (evict-first: don't pollute L2).
// ---------------------------------------------------------------------------
__global__ void __launch_bounds__(256)
bcast_kernel(float* __restrict__ out)
{
    const int chunk = blockIdx.x;
    const int b     = blockIdx.y;

    float4 v = ((const float4*)g_row)[b * 256 + threadIdx.x];
    float4* op = (float4*)out + ((size_t)b * Tv + chunk * 8) * 256 + threadIdx.x;
    stcs128(op + 0 * 256, v);  stcs128(op + 1 * 256, v);
    stcs128(op + 2 * 256, v);  stcs128(op + 3 * 256, v);
    stcs128(op + 4 * 256, v);  stcs128(op + 5 * 256, v);
    stcs128(op + 6 * 256, v);  stcs128(op + 7 * 256, v);
}

// ---------------------------------------------------------------------------
extern "C" void kernel_launch(void* const* d_in, const int* in_sizes, int n_in,
                              void* d_out, int out_size)
{
    const float* x  = (const float*)d_in[0];
    const float* Wv = (const float*)d_in[5];
    const float* bv = (const float*)d_in[6];
    const float* Wo = (const float*)d_in[7];
    const float* bo = (const float*)d_in[8];
    float* out = (float*)d_out;

    xsum_part_kernel<<<dim3(NCHUNK, 8), 256>>>(x);
    vsum_part_kernel<<<dim3(8, 16), 256>>>(Wv);
    row_kernel<<<32, 256>>>(Wo, bv, bo);
    bcast_kernel<<<dim3(NCHUNK, 8), 256>>>(out);
}